// round 9
// baseline (speedup 1.0000x reference)
#include <cuda_runtime.h>
#include <cstdint>

#define BATCH 64
#define DIM 1024
#define ROWS 32     // rows per fused block

// ---- scratch (device globals; no allocations allowed) ----
__device__ float g_acc[3][BATCH * DIM];   // 0=qp, 1=kp, 2=g2 (one memset zeroes all)
__device__ float g_w1s[DIM];

typedef unsigned long long u64;

__device__ __forceinline__ float frcp(float x) {
    float r; asm("rcp.approx.f32 %0, %1;" : "=f"(r) : "f"(x)); return r;
}
__device__ __forceinline__ float fex2(float x) {
    float r; asm("ex2.approx.f32 %0, %1;" : "=f"(r) : "f"(x)); return r;
}
__device__ __forceinline__ float ftanh(float x) {
    float r; asm("tanh.approx.f32 %0, %1;" : "=f"(r) : "f"(x)); return r;
}
__device__ __forceinline__ u64 pk(float lo, float hi) {
    u64 d; asm("mov.b64 %0, {%1, %2};" : "=l"(d)
               : "r"(__float_as_uint(lo)), "r"(__float_as_uint(hi)));
    return d;
}
__device__ __forceinline__ void upk(float& lo, float& hi, u64 d) {
    unsigned a, b;
    asm("mov.b64 {%0, %1}, %2;" : "=r"(a), "=r"(b) : "l"(d));
    lo = __uint_as_float(a); hi = __uint_as_float(b);
}
__device__ __forceinline__ u64 fma2(u64 a, u64 b, u64 c) {
    u64 d; asm("fma.rn.f32x2 %0, %1, %2, %3;" : "=l"(d) : "l"(a), "l"(b), "l"(c));
    return d;
}
__device__ __forceinline__ u64 mul2(u64 a, u64 b) {
    u64 d; asm("mul.rn.f32x2 %0, %1, %2;" : "=l"(d) : "l"(a), "l"(b));
    return d;
}
__device__ __forceinline__ u64 add2(u64 a, u64 b) {
    u64 d; asm("add.rn.f32x2 %0, %1, %2;" : "=l"(d) : "l"(a), "l"(b));
    return d;
}
__device__ __forceinline__ void red4(float* addr, float a, float b, float c, float d) {
    asm volatile("red.global.v4.f32.add [%0], {%1, %2, %3, %4};"
                 :: "l"(addr), "f"(a), "f"(b), "f"(c), "f"(d) : "memory");
}

// ---------------------------------------------------------------------------
// Split-K GEMM, atomic accumulation (buffers pre-zeroed by cudaMemsetAsync).
// sel 0: qp = q @ Wq^T (+bq)   sel 1: kp = k @ Wk^T (+bk)   sel 2: g2 = kp @ W2^T (+bg)
// Tile 64(M) x 64(N); K-chunk = DIM / gridDim.y.
// blockIdx.x == 16 (first launch only): spare blocks compute w1s row sums.
// ---------------------------------------------------------------------------
__global__ __launch_bounds__(256) void gemm_atom(
    int sel_base,
    const float* __restrict__ q, const float* __restrict__ k,
    const float* __restrict__ Wq, const float* __restrict__ Wk,
    const float* __restrict__ Wg,
    const float* __restrict__ bq, const float* __restrict__ bk,
    const float* __restrict__ bg)
{
    // ---- spare blocks: w1s[j] = sum_c Wg[j, c < DIM] ----
    if (blockIdx.x == 16) {
        int id   = blockIdx.y + 16 * blockIdx.z;    // 0..31
        int w    = threadIdx.x >> 5;
        int lane = threadIdx.x & 31;
#pragma unroll
        for (int rr = 0; rr < 4; rr++) {
            int row = id * 32 + w + rr * 8;
            const float* rp = Wg + (size_t)row * (2 * DIM);
            float s = 0.f;
#pragma unroll
            for (int i = 0; i < 8; i++) {
                float4 v = *reinterpret_cast<const float4*>(&rp[lane * 4 + i * 128]);
                s += v.x + v.y + v.z + v.w;
            }
#pragma unroll
            for (int o = 16; o; o >>= 1) s += __shfl_xor_sync(0xffffffffu, s, o);
            if (lane == 0) g_w1s[row] = s;
        }
        return;
    }

    int sel = sel_base + blockIdx.z;
    const float* in;
    const float* W;
    const float* bias;
    float* dst = &g_acc[sel][0];
    int ld, off;
    if (sel == 0)      { in = q;           W = Wq; ld = DIM;     off = 0;   bias = bq; }
    else if (sel == 1) { in = k;           W = Wk; ld = DIM;     off = 0;   bias = bk; }
    else               { in = &g_acc[1][0]; W = Wg; ld = 2 * DIM; off = DIM; bias = bg; }

    const int kchunk = DIM / gridDim.y;
    const int o0 = blockIdx.x * 64;
    const int k0 = blockIdx.y * kchunk;

    __shared__ __align__(16) float As[32][68];  // [k][m]
    __shared__ __align__(16) float Bs[32][68];  // [k][n]

    const int t  = threadIdx.x;
    const int tx = t & 15;   // n / 4
    const int ty = t >> 4;   // m / 4
    const int m0 = t >> 3;   // 0..31
    const int kq = t & 7;    // 0..7

    float acc[4][4];
#pragma unroll
    for (int i = 0; i < 4; i++)
#pragma unroll
        for (int j = 0; j < 4; j++) acc[i][j] = 0.f;

    // prefetch first chunk
    float4 va0, va1, vb0, vb1;
    {
        const float* ain = &in[k0 + kq * 4];
        const float* win = &W[(size_t)o0 * ld + off + k0 + kq * 4];
        va0 = *reinterpret_cast<const float4*>(&ain[(size_t)m0 * DIM]);
        va1 = *reinterpret_cast<const float4*>(&ain[(size_t)(m0 + 32) * DIM]);
        vb0 = *reinterpret_cast<const float4*>(&win[(size_t)m0 * ld]);
        vb1 = *reinterpret_cast<const float4*>(&win[(size_t)(m0 + 32) * ld]);
    }

    for (int kc = 0; kc < kchunk; kc += 32) {
        if (kc) __syncthreads();
        As[kq * 4 + 0][m0] = va0.x; As[kq * 4 + 1][m0] = va0.y;
        As[kq * 4 + 2][m0] = va0.z; As[kq * 4 + 3][m0] = va0.w;
        As[kq * 4 + 0][m0 + 32] = va1.x; As[kq * 4 + 1][m0 + 32] = va1.y;
        As[kq * 4 + 2][m0 + 32] = va1.z; As[kq * 4 + 3][m0 + 32] = va1.w;
        Bs[kq * 4 + 0][m0] = vb0.x; Bs[kq * 4 + 1][m0] = vb0.y;
        Bs[kq * 4 + 2][m0] = vb0.z; Bs[kq * 4 + 3][m0] = vb0.w;
        Bs[kq * 4 + 0][m0 + 32] = vb1.x; Bs[kq * 4 + 1][m0 + 32] = vb1.y;
        Bs[kq * 4 + 2][m0 + 32] = vb1.z; Bs[kq * 4 + 3][m0 + 32] = vb1.w;
        __syncthreads();
        if (kc + 32 < kchunk) {
            const float* ain = &in[k0 + kc + 32 + kq * 4];
            const float* win = &W[(size_t)o0 * ld + off + k0 + kc + 32 + kq * 4];
            va0 = *reinterpret_cast<const float4*>(&ain[(size_t)m0 * DIM]);
            va1 = *reinterpret_cast<const float4*>(&ain[(size_t)(m0 + 32) * DIM]);
            vb0 = *reinterpret_cast<const float4*>(&win[(size_t)m0 * ld]);
            vb1 = *reinterpret_cast<const float4*>(&win[(size_t)(m0 + 32) * ld]);
        }
#pragma unroll
        for (int kk = 0; kk < 32; kk++) {
            float4 a  = *reinterpret_cast<const float4*>(&As[kk][ty * 4]);
            float4 bv = *reinterpret_cast<const float4*>(&Bs[kk][tx * 4]);
            acc[0][0] = fmaf(a.x, bv.x, acc[0][0]);
            acc[0][1] = fmaf(a.x, bv.y, acc[0][1]);
            acc[0][2] = fmaf(a.x, bv.z, acc[0][2]);
            acc[0][3] = fmaf(a.x, bv.w, acc[0][3]);
            acc[1][0] = fmaf(a.y, bv.x, acc[1][0]);
            acc[1][1] = fmaf(a.y, bv.y, acc[1][1]);
            acc[1][2] = fmaf(a.y, bv.z, acc[1][2]);
            acc[1][3] = fmaf(a.y, bv.w, acc[1][3]);
            acc[2][0] = fmaf(a.z, bv.x, acc[2][0]);
            acc[2][1] = fmaf(a.z, bv.y, acc[2][1]);
            acc[2][2] = fmaf(a.z, bv.z, acc[2][2]);
            acc[2][3] = fmaf(a.z, bv.w, acc[2][3]);
            acc[3][0] = fmaf(a.w, bv.x, acc[3][0]);
            acc[3][1] = fmaf(a.w, bv.y, acc[3][1]);
            acc[3][2] = fmaf(a.w, bv.z, acc[3][2]);
            acc[3][3] = fmaf(a.w, bv.w, acc[3][3]);
        }
    }

    // split 0 carries the bias
    if (blockIdx.y == 0) {
        float b0 = bias[o0 + tx * 4 + 0];
        float b1 = bias[o0 + tx * 4 + 1];
        float b2 = bias[o0 + tx * 4 + 2];
        float b3 = bias[o0 + tx * 4 + 3];
#pragma unroll
        for (int i = 0; i < 4; i++) {
            acc[i][0] += b0; acc[i][1] += b1; acc[i][2] += b2; acc[i][3] += b3;
        }
    }

#pragma unroll
    for (int i = 0; i < 4; i++)
        red4(&dst[(ty * 4 + i) * DIM + o0 + tx * 4],
             acc[i][0], acc[i][1], acc[i][2], acc[i][3]);
}

// ---------------------------------------------------------------------------
// Fused scores*gate + softmax — HALF-ROW WARP PAIRS.
// A row is split across 2 warps: warp-half h covers j = h*512 + lane*4 + c*128,
// c = 0..3 (16 elems/thread, ep[8] u64 — half the registers of R8).
// Pair sum: 5 shfl + double-buffered smem slot + named barrier (2 warps only;
// no block-wide coupling). Coefficients in smem (12 KB), math packed f32x2.
// Block = 256 thr = 4 pairs; each pair does 8 rows. grid = (64, 32).
// ---------------------------------------------------------------------------
__global__ __launch_bounds__(256) void fused_softmax(float* __restrict__ out)
{
    const int b   = blockIdx.x;
    const int i0  = blockIdx.y * ROWS;
    const int tid = threadIdx.x;

    __shared__ __align__(16) float s_ap[DIM];
    __shared__ __align__(16) float s_cw[DIM];
    __shared__ __align__(16) float s_cg[DIM];
    __shared__ float qs[ROWS];
    __shared__ float ps[2][4][2];   // [buf][pair][half]

    const float L2E = 1.4426950408889634f;
    // deg-5 minimax odd poly for sigma(u)-0.5, u in [-1,1] (err ~5e-6)
    const float A1 = 0.2499814f, A3 = -0.02068092f, A5 = 0.00176246f;
    const u64 A1p = pk(A1, A1), A3p = pk(A3, A3), A5p = pk(A5, A5);
    const u64 HALFp = pk(0.5f, 0.5f);

    // fill coefficient smem (each thread one float4 per array)
    {
        const int j0 = tid * 4;
        float4 kpv = *reinterpret_cast<const float4*>(&g_acc[1][b * DIM + j0]);
        float4 wv  = *reinterpret_cast<const float4*>(&g_w1s[j0]);
        float4 gv  = *reinterpret_cast<const float4*>(&g_acc[2][b * DIM + j0]);
        *reinterpret_cast<float4*>(&s_ap[j0]) =
            make_float4(kpv.x * L2E, kpv.y * L2E, kpv.z * L2E, kpv.w * L2E);
        *reinterpret_cast<float4*>(&s_cw[j0]) =
            make_float4(wv.x * 0.5f, wv.y * 0.5f, wv.z * 0.5f, wv.w * 0.5f);
        *reinterpret_cast<float4*>(&s_cg[j0]) =
            make_float4(gv.x * 0.5f, gv.y * 0.5f, gv.z * 0.5f, gv.w * 0.5f);
        if (tid < ROWS) qs[tid] = g_acc[0][b * DIM + i0 + tid];
    }
    __syncthreads();

    const int w    = tid >> 5, lane = tid & 31;
    const int half = w & 1;           // which 512-wide half of the row
    const int pair = w >> 1;          // 0..3
    const int jbase = half * 512 + lane * 4;

#pragma unroll 1
    for (int rr = 0; rr < 8; rr++) {
        const int r = pair + rr * 4;
        const float qi = qs[r];
        const u64 qip = pk(qi, qi);

        u64 ep[8];
        u64 sum2 = 0;  // packed 0.0,0.0
#pragma unroll
        for (int c = 0; c < 4; c++) {
            const int j = jbase + c * 128;
            float4 av = *reinterpret_cast<const float4*>(&s_ap[j]);
            float4 wv = *reinterpret_cast<const float4*>(&s_cw[j]);
            float4 gv = *reinterpret_cast<const float4*>(&s_cg[j]);
#pragma unroll
            for (int p = 0; p < 2; p++) {
                const u64 cwp = p ? pk(wv.z, wv.w) : pk(wv.x, wv.y);
                const u64 cgp = p ? pk(gv.z, gv.w) : pk(gv.x, gv.y);
                const u64 app = p ? pk(av.z, av.w) : pk(av.x, av.y);
                u64 argp = fma2(qip, cwp, cgp);              // gate_pre / 2
                float a0, a1; upk(a0, a1, argp);
                float th0 = ftanh(a0), th1 = ftanh(a1);
                u64 s1p = fma2(pk(th0, th1), HALFp, HALFp);  // inner sigmoid
                u64 z2  = mul2(s1p, s1p);
                u64 pp  = fma2(z2, A5p, A3p);                // minimax deg-5
                pp      = fma2(z2, pp, A1p);
                u64 gatep = fma2(s1p, pp, HALFp);            // outer sigmoid
                u64 eargp = mul2(mul2(qip, app), gatep);     // L2E*score*gate
                float e0a, e1a; upk(e0a, e1a, eargp);
                u64 ev = pk(fex2(e0a), fex2(e1a));
                ep[c * 2 + p] = ev;
                sum2 = add2(sum2, ev);
            }
        }
        float slo, shi; upk(slo, shi, sum2);
        float loc = slo + shi;
#pragma unroll
        for (int o = 16; o; o >>= 1) loc += __shfl_xor_sync(0xffffffffu, loc, o);
        if (lane == 0) ps[rr & 1][pair][half] = loc;
        asm volatile("bar.sync %0, 64;" :: "r"(1 + pair) : "memory");
        const float tot = ps[rr & 1][pair][0] + ps[rr & 1][pair][1];
        const float inv = frcp(tot);
        const u64 invp = pk(inv, inv);

        float* orow = out + ((size_t)(b * DIM + i0 + r)) * DIM + jbase;
#pragma unroll
        for (int c = 0; c < 4; c++) {
            u64 o0v = mul2(ep[c * 2 + 0], invp);
            u64 o1v = mul2(ep[c * 2 + 1], invp);
            asm volatile("st.global.cs.v2.b64 [%0], {%1, %2};"
                         :: "l"(orow + c * 128), "l"(o0v), "l"(o1v) : "memory");
        }
    }
}

extern "C" void kernel_launch(void* const* d_in, const int* in_sizes, int n_in,
                              void* d_out, int out_size)
{
    const float* q  = (const float*)d_in[0];
    const float* k  = (const float*)d_in[1];
    // d_in[2] = v : unused by the reference
    const float* Wq = (const float*)d_in[3];
    const float* bq = (const float*)d_in[4];
    const float* Wk = (const float*)d_in[5];
    const float* bk = (const float*)d_in[6];
    const float* Wg = (const float*)d_in[7];
    const float* bg = (const float*)d_in[8];
    float* out = (float*)d_out;

    // L0: zero all accumulators with one memset node (graph-capturable)
    void* acc_ptr = nullptr;
    cudaGetSymbolAddress(&acc_ptr, g_acc);
    cudaMemsetAsync(acc_ptr, 0, sizeof(float) * 3 * BATCH * DIM);

    // L1: qp & kp (atomic split-K, KSPLIT=16) + w1s in spare blocks (x==16)
    gemm_atom<<<dim3(17, 16, 2), 256>>>(0, q, k, Wq, Wk, Wg, bq, bk, bg);
    // L2: g2 = kp @ W2^T (atomic split-K, KSPLIT=32)
    gemm_atom<<<dim3(16, 32, 1), 256>>>(2, q, k, Wq, Wk, Wg, bq, bk, bg);
    // L3: fused scores/gate/softmax — one pass over the 256 MB output
    fused_softmax<<<dim3(BATCH, DIM / ROWS), 256>>>(out);
}